// round 5
// baseline (speedup 1.0000x reference)
#include <cuda_runtime.h>
#include <cstdint>

// SpatialConv implicit GEMM, tf32 mma.sync, cp.async double-buffered.
// CTA: 128 Co x 256 px (4 rows), 512 thr, 16 warps (4m x 4n), warp 32x64.
// K order: k-step kb -> tap (kb%5) over 8 channels (cbase + lane K-index).
// taps: 0:(0,0) 1:(-1,0) 2:(0,-1) 3:(0,1) 4:(1,0)

#define CI 256
#define CO 256
#define HH 64
#define WW 64
#define NB 16
#define KTOT 1280
#define BM 128
#define NTH 512
#define CCH 16          // channels per chunk
#define CK 80           // K per chunk (10 k8-steps)
#define NCHK 16
#define AST 84          // A stride (floats): gid*20+tig*5 distinct mod 32
#define CST 440         // X per-channel stride: tig*24(+gid) distinct mod 32
#define AFL (BM * AST)  // 10752 floats per A buf
#define XFL (CCH * CST) // 7040 floats per X buf
#define DYN ((2 * AFL + 2 * XFL) * 4)  // 142336 B

__device__ __forceinline__ uint32_t f2tf(float f) {
    uint32_t u; asm("cvt.rna.tf32.f32 %0, %1;" : "=r"(u) : "f"(f)); return u;
}
__device__ __forceinline__ void cpa16(uint32_t dst, const void* src, int srcsz) {
    asm volatile("cp.async.cg.shared.global [%0], [%1], 16, %2;"
                 :: "r"(dst), "l"(src), "r"(srcsz));
}

__global__ __launch_bounds__(NTH, 1)
void conv_mma_kernel(const float* __restrict__ x,
                     const float* __restrict__ wt,
                     float* __restrict__ out)
{
    extern __shared__ float sm[];
    const int tid  = threadIdx.x;
    const int lane = tid & 31, wid = tid >> 5;
    const int wm   = wid >> 2;    // 0..3: co warp tile
    const int wn   = wid & 3;     // 0..3: output row in quad
    const int gid  = lane >> 2, tig = lane & 3;
    const int cob  = blockIdx.x * BM;
    const int h0   = blockIdx.y * 4;
    const int n    = blockIdx.z;

    float* A_[2] = {sm, sm + AFL};
    float* X_[2] = {sm + 2 * AFL, sm + 2 * AFL + XFL};
    const uint32_t smB = (uint32_t)__cvta_generic_to_shared(sm);
    const uint32_t aB[2] = {smB, smB + AFL * 4};
    const uint32_t xB[2] = {smB + 2 * AFL * 4, smB + (2 * AFL + XFL) * 4};

    // zero X border cols (0..3, 68..71) for all 6 rows, both buffers
    for (int e = tid; e < 2 * CCH * 6 * 8; e += NTH) {
        int b = e / (CCH * 6 * 8), r2 = e % (CCH * 6 * 8);
        int c = r2 / 48, r = (r2 >> 3) % 6, q = r2 & 7;
        X_[b][c * CST + r * 72 + ((q < 4) ? q : (64 + q))] = 0.f;
    }

    float acc[2][8][4];
#pragma unroll
    for (int mi = 0; mi < 2; mi++)
#pragma unroll
        for (int ni = 0; ni < 8; ni++)
#pragma unroll
            for (int r = 0; r < 4; r++) acc[mi][ni][r] = 0.f;

    auto stage = [&](int ch, int buf) {
        // A: 128 o x 80 ck = 2560 x 16B, 5 per thread
#pragma unroll
        for (int i = 0; i < 5; i++) {
            int e = tid + i * NTH;
            int o = e / 20, q = e % 20;
            cpa16(aB[buf] + (uint32_t)((o * AST + q * 4) * 4),
                  wt + (size_t)(cob + o) * KTOT + ch * CK + q * 4, 16);
        }
        // X: 16 ch x 6 rows (h0-1..h0+4) x 64 px = 1536 x 16B, 3 per thread
#pragma unroll
        for (int i = 0; i < 3; i++) {
            int e = tid + i * NTH;
            int c = e / 96, r = (e >> 4) % 6, q = e & 15;
            int gh = h0 - 1 + r;
            int ok = ((unsigned)gh < HH) ? 16 : 0;
            int ghc = ok ? gh : 0;
            cpa16(xB[buf] + (uint32_t)((c * CST + r * 72 + 4 + q * 4) * 4),
                  x + (((size_t)n * CI + ch * CCH + c) * HH + ghc) * WW + q * 4, ok);
        }
    };

    stage(0, 0);
    asm volatile("cp.async.commit_group;");

    const int ROW[5] = {1, 0, 1, 1, 2};
    const int DX5[5] = {0, 0, -1, 1, 0};

    for (int chk = 0; chk < NCHK; chk++) {
        const int buf = chk & 1;
        if (chk + 1 < NCHK) stage(chk + 1, buf ^ 1);
        asm volatile("cp.async.commit_group;");
        asm volatile("cp.async.wait_group 1;");
        __syncthreads();

        const float* A = A_[buf];
        const float* X = X_[buf];

#pragma unroll
        for (int kb = 0; kb < 10; kb++) {
            const int tap = (kb < 5) ? kb : (kb - 5);
            const int cb  = (kb < 5) ? 0 : 8;
            const int rr  = ROW[tap] + wn;
            const int dx  = DX5[tap];

            uint32_t a[2][4], b[8][2];
#pragma unroll
            for (int mi = 0; mi < 2; mi++) {
                int r  = wm * 32 + mi * 16 + gid;
                int cl = (cb + tig) * 5 + tap;
                int c2 = (cb + tig + 4) * 5 + tap;
                a[mi][0] = f2tf(A[r * AST + cl]);
                a[mi][1] = f2tf(A[(r + 8) * AST + cl]);
                a[mi][2] = f2tf(A[r * AST + c2]);
                a[mi][3] = f2tf(A[(r + 8) * AST + c2]);
            }
#pragma unroll
            for (int ni = 0; ni < 8; ni++) {
                int cc = ni * 8 + gid + 4 + dx;
                b[ni][0] = f2tf(X[(cb + tig) * CST + rr * 72 + cc]);
                b[ni][1] = f2tf(X[(cb + tig + 4) * CST + rr * 72 + cc]);
            }
#pragma unroll
            for (int mi = 0; mi < 2; mi++)
#pragma unroll
                for (int ni = 0; ni < 8; ni++) {
                    asm volatile(
                        "mma.sync.aligned.m16n8k8.row.col.f32.tf32.tf32.f32 "
                        "{%0,%1,%2,%3}, {%4,%5,%6,%7}, {%8,%9}, {%0,%1,%2,%3};"
                        : "+f"(acc[mi][ni][0]), "+f"(acc[mi][ni][1]),
                          "+f"(acc[mi][ni][2]), "+f"(acc[mi][ni][3])
                        : "r"(a[mi][0]), "r"(a[mi][1]), "r"(a[mi][2]), "r"(a[mi][3]),
                          "r"(b[ni][0]), "r"(b[ni][1]));
                }
        }
        __syncthreads();
    }

    // epilogue: warp wn owns row h0+wn
    const int h = h0 + wn;
#pragma unroll
    for (int mi = 0; mi < 2; mi++) {
        int co0 = cob + wm * 32 + mi * 16 + gid;
#pragma unroll
        for (int ni = 0; ni < 8; ni++) {
            int c0 = ni * 8 + tig * 2;
            *(float2*)&out[(((size_t)n * CO + co0) * HH + h) * WW + c0] =
                make_float2(acc[mi][ni][0], acc[mi][ni][1]);
            *(float2*)&out[(((size_t)n * CO + co0 + 8) * HH + h) * WW + c0] =
                make_float2(acc[mi][ni][2], acc[mi][ni][3]);
        }
    }
}

extern "C" void kernel_launch(void* const* d_in, const int* in_sizes, int n_in,
                              void* d_out, int out_size)
{
    const float* x  = (const float*)d_in[0];
    const float* wt = (const float*)d_in[1];
    float* out = (float*)d_out;

    cudaFuncSetAttribute(conv_mma_kernel,
                         cudaFuncAttributeMaxDynamicSharedMemorySize, DYN);
    dim3 grid(CO / BM, HH / 4, NB);   // (2, 16, 16) = 512 CTAs
    conv_mma_kernel<<<grid, NTH, DYN>>>(x, wt, out);
}